// round 3
// baseline (speedup 1.0000x reference)
#include <cuda_runtime.h>
#include <cstdint>

// ---------------------------------------------------------------------------
// Implicit GEMM for segmented Conv4d (kernel 3x3 over (S,t), pointwise h,w).
//   x: (8, 1024, 4, 14, 14) fp32    W: (1024, 1024, 3, 3) fp32   out: like x
//   b = b'*4 + s, b' in [0,2). Padded cell grid per b': 6 x 6 cells of 196 px.
//   Xt row r = ((b'*6+s')*6+t')*196 + p, ci contiguous (pad cells zeroed).
//   Output q = b*784 + t*196 + p in [0,6272);
//   rbase(q) = b'*7056 + s*1176 + t*196 + p ; tap (ks,kt) adds ks*1176+kt*196.
//   y[q,co] = sum_{tap,ci} Wt[tap][co][ci] * Xt[rbase+off(tap)][ci]  + x
// Base sm_100 ISA only: cp.async + mma.sync.m16n8k8.tf32 (no tcgen05).
// ---------------------------------------------------------------------------
#define CIN      1024
#define COUT     1024
#define XTROWS   14112
#define MT       256            // CTA M tile (co)
#define NT       128            // CTA N tile (q)
#define MTILES   4
#define NTILES   49
#define ITERS    288            // 9 taps * 32-wide ci chunks
#define STAGES   4
#define APAD     36             // 32 floats + 4 pad (16B-aligned rows)
#define A_BYTES  (MT * APAD * 4)       // 36864
#define B_BYTES  (NT * APAD * 4)       // 18432
#define STAGE_BYTES (A_BYTES + B_BYTES) // 55296
#define OFF_RBASE 0             // 128 ints
#define OFF_STAGE 1024
#define SMEM_MAIN (OFF_STAGE + STAGES * STAGE_BYTES)  // 222208

__device__ float g_Xt[XTROWS * CIN];    // 57.8 MB padded transposed input (tf32)
__device__ float g_Wt[9 * COUT * CIN];  // 37.7 MB per-tap K-major weights (tf32)

// ----------------------------- helpers -------------------------------------
__device__ __forceinline__ unsigned s2u(const void* p) {
    unsigned a;
    asm("{ .reg .u64 t; cvta.to.shared.u64 t, %1; cvt.u32.u64 %0, t; }" : "=r"(a) : "l"(p));
    return a;
}
__device__ __forceinline__ float to_tf32(float f) {
    unsigned u; asm("cvt.rna.tf32.f32 %0, %1;" : "=r"(u) : "f"(f));
    return __uint_as_float(u);
}
__device__ __forceinline__ void cp16(unsigned s, const void* g) {
    asm volatile("cp.async.cg.shared.global [%0], [%1], 16;" :: "r"(s), "l"(g) : "memory");
}
__device__ __forceinline__ void cp_commit() {
    asm volatile("cp.async.commit_group;" ::: "memory");
}
__device__ __forceinline__ void cp_wait2() {
    asm volatile("cp.async.wait_group 2;" ::: "memory");
}
__device__ __forceinline__ void mma_tf32(float* c, const unsigned* a, const unsigned* b) {
    asm volatile(
        "mma.sync.aligned.m16n8k8.row.col.f32.tf32.tf32.f32 "
        "{%0,%1,%2,%3}, {%4,%5,%6,%7}, {%8,%9}, {%0,%1,%2,%3};"
        : "+f"(c[0]), "+f"(c[1]), "+f"(c[2]), "+f"(c[3])
        : "r"(a[0]), "r"(a[1]), "r"(a[2]), "r"(a[3]), "r"(b[0]), "r"(b[1]));
}

// ----------------------------- prep kernels --------------------------------
__global__ void prep_x(const float* __restrict__ x) {
    __shared__ float sm[32 * 197];
    int cell = blockIdx.x;              // (b'*6 + s')*6 + t'
    int ci0 = blockIdx.y * 32;
    int bp = cell / 36;
    int sp = (cell / 6) % 6;
    int tp = cell % 6;
    int rbase = cell * 196;
    int tid = threadIdx.x;
    bool pad = (sp == 0) | (sp == 5) | (tp == 0) | (tp == 5);
    if (!pad) {
        int b = bp * 4 + (sp - 1);
        int t = tp - 1;
        long xbase = (long)(b * CIN + ci0) * 784 + t * 196;
        for (int l = tid; l < 32 * 196; l += 256) {
            int i = l / 196, p = l - i * 196;
            sm[i * 197 + p] = to_tf32(x[xbase + (long)i * 784 + p]);
        }
        __syncthreads();
        for (int l = tid; l < 32 * 196; l += 256) {
            int p = l >> 5, i = l & 31;
            g_Xt[(long)(rbase + p) * CIN + ci0 + i] = sm[i * 197 + p];
        }
    } else {
        for (int l = tid; l < 32 * 196; l += 256) {
            int p = l >> 5, i = l & 31;
            g_Xt[(long)(rbase + p) * CIN + ci0 + i] = 0.0f;
        }
    }
}

__global__ void prep_w(const float* __restrict__ W) {
    long t = (long)blockIdx.x * 256 + threadIdx.x;   // co*1024 + ci
    const float* p = W + t * 9;
    float v[9];
#pragma unroll
    for (int k = 0; k < 9; k++) v[k] = to_tf32(p[k]);
#pragma unroll
    for (int k = 0; k < 9; k++) g_Wt[(long)k * (COUT * CIN) + t] = v[k];
}

// ----------------------------- main GEMM -----------------------------------
__global__ void __launch_bounds__(256, 1) conv_main(const float* __restrict__ x,
                                                    float* __restrict__ out) {
    extern __shared__ __align__(16) char smem[];
    const int tid = threadIdx.x, wid = tid >> 5, lid = tid & 31;
    const int gid = lid >> 2, tig = lid & 3;
    const int mtile = blockIdx.x, ntile = blockIdx.y;
    const int wm = (wid >> 1) * 64;       // warp m offset in [0,256)
    const int wn = (wid & 1) * 64;        // warp n offset in [0,128)

    int* rbase_s = (int*)(smem + OFF_RBASE);
    if (tid < NT) {
        int q = ntile * NT + tid;
        int b = q / 784;
        int rem = q - b * 784;
        int t = rem / 196;
        int p = rem - t * 196;
        rbase_s[tid] = (b >> 2) * 7056 + (b & 3) * 1176 + t * 196 + p;
    }
    __syncthreads();

    // per-thread producer addresses (byte offsets)
    unsigned gA[8], sA[8], gB[4], sB[4];
#pragma unroll
    for (int k = 0; k < 8; k++) {
        int c = tid + 256 * k;            // A chunk 0..2047
        int row = c >> 3, j = c & 7;
        gA[k] = (unsigned)((mtile * MT + row) * 4096 + j * 16);
        sA[k] = (unsigned)(OFF_STAGE + row * (APAD * 4) + j * 16);
    }
#pragma unroll
    for (int k = 0; k < 4; k++) {
        int c = tid + 256 * k;            // B chunk 0..1023
        int n = c >> 3, j = c & 7;
        gB[k] = (unsigned)(rbase_s[n] * 4096 + j * 16);
        sB[k] = (unsigned)(OFF_STAGE + A_BYTES + n * (APAD * 4) + j * 16);
    }
    const unsigned sb = s2u(smem);
    const char* WtB = (const char*)g_Wt;
    const char* XtB = (const char*)g_Xt;

    float acc[4][8][4];
#pragma unroll
    for (int i = 0; i < 4; i++)
#pragma unroll
        for (int j = 0; j < 8; j++)
#pragma unroll
            for (int k = 0; k < 4; k++) acc[i][j][k] = 0.0f;

    auto issue = [&](int it) {
        if (it < ITERS) {
            int tap = it >> 5, kc = it & 31;
            int ks = tap / 3, kt = tap - ks * 3;
            unsigned soA = (unsigned)tap * 4194304u + (unsigned)kc * 128u;
            unsigned soB = (unsigned)(ks * 1176 + kt * 196) * 4096u + (unsigned)kc * 128u;
            unsigned st = (unsigned)(it & (STAGES - 1)) * STAGE_BYTES;
#pragma unroll
            for (int k = 0; k < 8; k++) cp16(sb + sA[k] + st, WtB + gA[k] + soA);
#pragma unroll
            for (int k = 0; k < 4; k++) cp16(sb + sB[k] + st, XtB + gB[k] + soB);
        }
        cp_commit();
    };

    issue(0); issue(1); issue(2);

#pragma unroll 1
    for (int it = 0; it < ITERS; ++it) {
        cp_wait2();
        __syncthreads();
        issue(it + 3);
        const unsigned* As =
            (const unsigned*)(smem + OFF_STAGE + (it & (STAGES - 1)) * STAGE_BYTES);
        const unsigned* Bs = As + MT * APAD;
#pragma unroll
        for (int kk = 0; kk < 4; kk++) {
            unsigned a[4][4], b[8][2];
#pragma unroll
            for (int im = 0; im < 4; im++) {
                int base = (wm + im * 16 + gid) * APAD + kk * 8 + tig;
                a[im][0] = As[base];
                a[im][1] = As[base + 8 * APAD];
                a[im][2] = As[base + 4];
                a[im][3] = As[base + 8 * APAD + 4];
            }
#pragma unroll
            for (int in = 0; in < 8; in++) {
                int base = (wn + in * 8 + gid) * APAD + kk * 8 + tig;
                b[in][0] = Bs[base];
                b[in][1] = Bs[base + 4];
            }
#pragma unroll
            for (int im = 0; im < 4; im++)
#pragma unroll
                for (int in = 0; in < 8; in++) mma_tf32(acc[im][in], a[im], b[in]);
        }
    }

    // ------------------------- epilogue: residual add -----------------------
#pragma unroll
    for (int im = 0; im < 4; im++) {
        int m0 = mtile * MT + wm + im * 16 + gid;     // co row (and +8)
#pragma unroll
        for (int in = 0; in < 8; in++) {
            int q = ntile * NT + wn + in * 8 + 2 * tig;   // even => pair in-bounds
            int b = q / 784;
            int rem = q - b * 784;
            int off0 = b * 802816 + m0 * 784 + rem;
            int off1 = off0 + 8 * 784;
            float2 x0 = *(const float2*)(x + off0);
            float2 x1 = *(const float2*)(x + off1);
            float2 o0 = make_float2(acc[im][in][0] + x0.x, acc[im][in][1] + x0.y);
            float2 o1 = make_float2(acc[im][in][2] + x1.x, acc[im][in][3] + x1.y);
            *(float2*)(out + off0) = o0;
            *(float2*)(out + off1) = o1;
        }
    }
}

// ----------------------------- launch --------------------------------------
extern "C" void kernel_launch(void* const* d_in, const int* in_sizes, int n_in,
                              void* d_out, int out_size) {
    const float* x = (const float*)d_in[0];
    const float* W = (const float*)d_in[1];
    if (n_in >= 2 && in_sizes[0] != 8 * 1024 * 4 * 14 * 14) {  // robustness
        x = (const float*)d_in[1];
        W = (const float*)d_in[0];
    }
    float* out = (float*)d_out;

    prep_w<<<4096, 256>>>(W);
    dim3 gx(72, 32);
    prep_x<<<gx, 256>>>(x);

    cudaFuncSetAttribute(conv_main, cudaFuncAttributeMaxDynamicSharedMemorySize, SMEM_MAIN);
    dim3 grid(MTILES, NTILES);
    conv_main<<<grid, 256, SMEM_MAIN>>>(x, out);
}

// round 4
// speedup vs baseline: 1.2126x; 1.2126x over previous
#include <cuda_runtime.h>
#include <cstdint>

// ---------------------------------------------------------------------------
// Implicit GEMM for segmented Conv4d (3x3 over (S,t), pointwise h,w).
//   x: (8,1024,4,14,14) fp32   W: (1024,1024,3,3) fp32   out: like x
//   Xt row r = ((b'*6+s')*6+t')*196 + p, ci contiguous (pad cells zeroed).
//   q = b*784 + t*196 + p in [0,6272);  rbase(q) = b'*7056 + s*1176 + t*196 + p
//   tap (ks,kt) adds ks*1176 + kt*196.   y[q,co] = sum Wt[tap][co][.]*Xt[row][.] + x
// Base sm_100 ISA: cp.async + ldmatrix + mma.sync.m16n8k8.tf32.
// CTA tile 128(co) x 112(q), 4 warps (2x2, warp tile 64x56), 3-stage pipeline,
// 2 CTAs/SM, grid 8 x 56 = 448 -> wave factor 1.31 vs 2.0 before.
// ---------------------------------------------------------------------------
#define CIN      1024
#define COUT     1024
#define XTROWS   14112
#define MT       128
#define NT       112
#define MTILES   8
#define NTILES   56
#define ITERS    288            // 9 taps * 32-wide ci chunks
#define STAGES   3
#define APAD     36             // words per 32-float row (+4 pad)
#define ROWB     144            // APAD*4 bytes
#define A_BYTES  (MT * ROWB)    // 18432
#define B_BYTES  (NT * ROWB)    // 16128
#define STAGE_BYTES (A_BYTES + B_BYTES)  // 34560
#define OFF_STAGE 1024
#define SMEM_MAIN (OFF_STAGE + STAGES * STAGE_BYTES)   // 104704

__device__ float g_Xt[XTROWS * CIN];    // 57.8 MB padded transposed input (tf32)
__device__ float g_Wt[9 * COUT * CIN];  // 37.7 MB per-tap K-major weights (tf32)

// ----------------------------- helpers -------------------------------------
__device__ __forceinline__ unsigned s2u(const void* p) {
    unsigned a;
    asm("{ .reg .u64 t; cvta.to.shared.u64 t, %1; cvt.u32.u64 %0, t; }" : "=r"(a) : "l"(p));
    return a;
}
__device__ __forceinline__ float to_tf32(float f) {
    unsigned u; asm("cvt.rna.tf32.f32 %0, %1;" : "=r"(u) : "f"(f));
    return __uint_as_float(u);
}
__device__ __forceinline__ void cp16(unsigned s, const void* g) {
    asm volatile("cp.async.cg.shared.global [%0], [%1], 16;" :: "r"(s), "l"(g) : "memory");
}
__device__ __forceinline__ void cp_commit() {
    asm volatile("cp.async.commit_group;" ::: "memory");
}
__device__ __forceinline__ void cp_wait1() {
    asm volatile("cp.async.wait_group 1;" ::: "memory");
}
__device__ __forceinline__ void ldsm4(unsigned* d, unsigned a) {
    asm volatile("ldmatrix.sync.aligned.m8n8.x4.shared.b16 {%0,%1,%2,%3}, [%4];"
                 : "=r"(d[0]), "=r"(d[1]), "=r"(d[2]), "=r"(d[3]) : "r"(a));
}
__device__ __forceinline__ void ldsm2(unsigned* d, unsigned a) {
    asm volatile("ldmatrix.sync.aligned.m8n8.x2.shared.b16 {%0,%1}, [%2];"
                 : "=r"(d[0]), "=r"(d[1]) : "r"(a));
}
__device__ __forceinline__ void mma_tf32(float* c, const unsigned* a, const unsigned* b) {
    asm volatile(
        "mma.sync.aligned.m16n8k8.row.col.f32.tf32.tf32.f32 "
        "{%0,%1,%2,%3}, {%4,%5,%6,%7}, {%8,%9}, {%0,%1,%2,%3};"
        : "+f"(c[0]), "+f"(c[1]), "+f"(c[2]), "+f"(c[3])
        : "r"(a[0]), "r"(a[1]), "r"(a[2]), "r"(a[3]), "r"(b[0]), "r"(b[1]));
}

// ----------------------------- prep kernels --------------------------------
__global__ void prep_x(const float* __restrict__ x) {
    __shared__ float sm[32 * 197];
    int cell = blockIdx.x;              // (b'*6 + s')*6 + t'
    int ci0 = blockIdx.y * 32;
    int bp = cell / 36;
    int sp = (cell / 6) % 6;
    int tp = cell % 6;
    int rbase = cell * 196;
    int tid = threadIdx.x;
    bool pad = (sp == 0) | (sp == 5) | (tp == 0) | (tp == 5);
    if (!pad) {
        int b = bp * 4 + (sp - 1);
        int t = tp - 1;
        long xbase = (long)(b * CIN + ci0) * 784 + t * 196;
        for (int l = tid; l < 32 * 196; l += 256) {
            int i = l / 196, p = l - i * 196;
            sm[i * 197 + p] = to_tf32(x[xbase + (long)i * 784 + p]);
        }
        __syncthreads();
        for (int l = tid; l < 32 * 196; l += 256) {
            int p = l >> 5, i = l & 31;
            g_Xt[(long)(rbase + p) * CIN + ci0 + i] = sm[i * 197 + p];
        }
    } else {
        for (int l = tid; l < 32 * 196; l += 256) {
            int p = l >> 5, i = l & 31;
            g_Xt[(long)(rbase + p) * CIN + ci0 + i] = 0.0f;
        }
    }
}

__global__ void prep_w(const float* __restrict__ W) {
    long t = (long)blockIdx.x * 256 + threadIdx.x;   // co*1024 + ci
    const float* p = W + t * 9;
    float v[9];
#pragma unroll
    for (int k = 0; k < 9; k++) v[k] = to_tf32(p[k]);
#pragma unroll
    for (int k = 0; k < 9; k++) g_Wt[(long)k * (COUT * CIN) + t] = v[k];
}

// ----------------------------- main GEMM -----------------------------------
__global__ void __launch_bounds__(128, 2) conv_main(const float* __restrict__ x,
                                                    float* __restrict__ out) {
    extern __shared__ __align__(16) char smem[];
    const int tid = threadIdx.x, wid = tid >> 5, lid = tid & 31;
    const int gid = lid >> 2, tig = lid & 3;
    const int mtile = blockIdx.x, ntile = blockIdx.y;
    const int wm = (wid >> 1) * 64;     // warp m offset {0,64}
    const int wn = (wid & 1) * 56;      // warp n offset {0,56}

    __shared__ int rbase_s[NT];
    if (tid < NT) {
        int q = ntile * NT + tid;
        int b = q / 784;
        int rem = q - b * 784;
        int t = rem / 196;
        int p = rem - t * 196;
        rbase_s[tid] = (b >> 2) * 7056 + (b & 3) * 1176 + t * 196 + p;
    }
    __syncthreads();

    // producer cp.async addresses: A 1024 chunks (8/thr), B 896 chunks (7/thr)
    unsigned gA[8], sA[8], gB[7], sB[7];
#pragma unroll
    for (int k = 0; k < 8; k++) {
        int c = tid + 128 * k;
        int row = c >> 3, j = c & 7;
        gA[k] = (unsigned)((mtile * MT + row) * 4096 + j * 16);
        sA[k] = (unsigned)(OFF_STAGE + row * ROWB + j * 16);
    }
#pragma unroll
    for (int k = 0; k < 7; k++) {
        int c = tid + 128 * k;
        int n = c >> 3, j = c & 7;
        gB[k] = (unsigned)(rbase_s[n] * 4096 + j * 16);
        sB[k] = (unsigned)(OFF_STAGE + A_BYTES + n * ROWB + j * 16);
    }
    const unsigned sb = s2u(smem);
    const char* WtB = (const char*)g_Wt;
    const char* XtB = (const char*)g_Xt;

    // ldmatrix per-lane base addresses
    const int lm = lid >> 3, lr = lid & 7;
    const unsigned aBase = sb + OFF_STAGE + (unsigned)((wm + (lm & 1) * 8 + lr) * ROWB + (lm >> 1) * 16);
    const unsigned bBase = sb + OFF_STAGE + A_BYTES + (unsigned)((wn + (lm >> 1) * 8 + lr) * ROWB + (lm & 1) * 16);
    const unsigned b6Base = sb + OFF_STAGE + A_BYTES + (unsigned)((wn + 48 + lr) * ROWB + (lm & 1) * 16);

    float acc[4][7][4];
#pragma unroll
    for (int i = 0; i < 4; i++)
#pragma unroll
        for (int j = 0; j < 7; j++)
#pragma unroll
            for (int k = 0; k < 4; k++) acc[i][j][k] = 0.0f;

    auto issue = [&](int it, int slot) {
        if (it < ITERS) {
            int tap = it >> 5, kc = it & 31;
            int ks = tap / 3, kt = tap - ks * 3;
            unsigned soA = (unsigned)tap * 4194304u + (unsigned)kc * 128u;
            unsigned soB = (unsigned)(ks * 1176 + kt * 196) * 4096u + (unsigned)kc * 128u;
            unsigned st = (unsigned)slot * STAGE_BYTES;
#pragma unroll
            for (int k = 0; k < 8; k++) cp16(sb + sA[k] + st, WtB + gA[k] + soA);
#pragma unroll
            for (int k = 0; k < 7; k++) cp16(sb + sB[k] + st, XtB + gB[k] + soB);
        }
        cp_commit();
    };

    issue(0, 0);
    issue(1, 1);

    int cs = 0, ps = 2;
#pragma unroll 1
    for (int it = 0; it < ITERS; ++it) {
        cp_wait1();
        __syncthreads();
        issue(it + 2, ps);
        ps = (ps == STAGES - 1) ? 0 : ps + 1;
        const unsigned stg = (unsigned)cs * STAGE_BYTES;
        cs = (cs == STAGES - 1) ? 0 : cs + 1;
#pragma unroll
        for (int kk = 0; kk < 4; kk++) {
            unsigned a[4][4], b[7][2];
#pragma unroll
            for (int im = 0; im < 4; im++)
                ldsm4(a[im], aBase + stg + (unsigned)(im * (16 * ROWB) + kk * 32));
#pragma unroll
            for (int p = 0; p < 3; p++) {
                unsigned d[4];
                ldsm4(d, bBase + stg + (unsigned)(p * (16 * ROWB) + kk * 32));
                b[2 * p][0] = d[0]; b[2 * p][1] = d[1];
                b[2 * p + 1][0] = d[2]; b[2 * p + 1][1] = d[3];
            }
            ldsm2(b[6], b6Base + stg + (unsigned)(kk * 32));
#pragma unroll
            for (int im = 0; im < 4; im++)
#pragma unroll
                for (int in = 0; in < 7; in++) mma_tf32(acc[im][in], a[im], b[in]);
        }
    }

    // ------------------------- epilogue: residual add -----------------------
#pragma unroll
    for (int im = 0; im < 4; im++) {
        int m0 = mtile * MT + wm + im * 16 + gid;       // co row (and +8)
#pragma unroll
        for (int in = 0; in < 7; in++) {
            int q = ntile * NT + wn + in * 8 + 2 * tig; // even start => pair in-bounds
            int b = q / 784;
            int rem = q - b * 784;
            int off0 = b * 802816 + m0 * 784 + rem;
            int off1 = off0 + 8 * 784;
            float2 x0 = *(const float2*)(x + off0);
            float2 x1 = *(const float2*)(x + off1);
            float2 o0 = make_float2(acc[im][in][0] + x0.x, acc[im][in][1] + x0.y);
            float2 o1 = make_float2(acc[im][in][2] + x1.x, acc[im][in][3] + x1.y);
            *(float2*)(out + off0) = o0;
            *(float2*)(out + off1) = o1;
        }
    }
}

// ----------------------------- launch --------------------------------------
extern "C" void kernel_launch(void* const* d_in, const int* in_sizes, int n_in,
                              void* d_out, int out_size) {
    const float* x = (const float*)d_in[0];
    const float* W = (const float*)d_in[1];
    if (n_in >= 2 && in_sizes[0] != 8 * 1024 * 4 * 14 * 14) {  // robustness
        x = (const float*)d_in[1];
        W = (const float*)d_in[0];
    }
    float* out = (float*)d_out;

    prep_w<<<4096, 256>>>(W);
    dim3 gx(72, 32);
    prep_x<<<gx, 256>>>(x);

    cudaFuncSetAttribute(conv_main, cudaFuncAttributeMaxDynamicSharedMemorySize, SMEM_MAIN);
    dim3 grid(MTILES, NTILES);
    conv_main<<<grid, 128, SMEM_MAIN>>>(x, out);
}

// round 6
// speedup vs baseline: 2.3056x; 1.9014x over previous
#include <cuda_runtime.h>
#include <cuda_fp16.h>
#include <cstdint>

// ---------------------------------------------------------------------------
// Implicit GEMM for segmented Conv4d (3x3 over (S,t), pointwise h,w) in fp16
// tensor cores (e5m10 has the same 10-bit mantissa as tf32 -> same accuracy).
//   x: (8,1024,4,14,14) fp32   W: (1024,1024,3,3) fp32   out: like x
//   Xt row r = ((b'*6+s')*6+t')*196 + p, ci contiguous (pad cells zeroed).
//   q = b*784 + t*196 + p;  rbase(q) = b'*7056 + s*1176 + t*196 + p
//   tap (ks,kt) adds ks*1176 + kt*196.  y[q,co] = sum Wt[tap][co][.]*Xt[row][.] + x
// Base sm_100 ISA: cp.async + ldmatrix.b16 + mma.sync.m16n8k16.f16 (f32 acc).
// CTA 128(co) x 112(q), 4 warps 2x2 (warp tile 64x56), K-chunk 64, 144 iters,
// 3-stage cp.async ring, 2 CTAs/SM, grid 8 x 56.
// ---------------------------------------------------------------------------
#define CIN      1024
#define COUT     1024
#define XTROWS   14112
#define MT       128
#define NT       112
#define MTILES   8
#define NTILES   56
#define ITERS    144            // 9 taps * 16 ci-chunks of 64
#define STAGES   3
#define ROWB     144            // 64 halves (128B) + 16B pad
#define A_BYTES  (MT * ROWB)    // 18432
#define B_BYTES  (NT * ROWB)    // 16128
#define STAGE_BYTES (A_BYTES + B_BYTES)  // 34560
#define OFF_STAGE 1024
#define SMEM_MAIN (OFF_STAGE + STAGES * STAGE_BYTES)   // 104704

__device__ __half g_Xt[XTROWS * CIN];    // 28.9 MB padded transposed input
__device__ __half g_Wt[9 * COUT * CIN];  // 18.9 MB per-tap K-major weights

// ----------------------------- helpers -------------------------------------
__device__ __forceinline__ unsigned s2u(const void* p) {
    unsigned a;
    asm("{ .reg .u64 t; cvta.to.shared.u64 t, %1; cvt.u32.u64 %0, t; }" : "=r"(a) : "l"(p));
    return a;
}
__device__ __forceinline__ void cp16(unsigned s, const void* g) {
    asm volatile("cp.async.cg.shared.global [%0], [%1], 16;" :: "r"(s), "l"(g) : "memory");
}
__device__ __forceinline__ void cp_commit() {
    asm volatile("cp.async.commit_group;" ::: "memory");
}
__device__ __forceinline__ void cp_wait1() {
    asm volatile("cp.async.wait_group 1;" ::: "memory");
}
__device__ __forceinline__ void ldsm4(unsigned* d, unsigned a) {
    asm volatile("ldmatrix.sync.aligned.m8n8.x4.shared.b16 {%0,%1,%2,%3}, [%4];"
                 : "=r"(d[0]), "=r"(d[1]), "=r"(d[2]), "=r"(d[3]) : "r"(a));
}
__device__ __forceinline__ void ldsm2(unsigned* d, unsigned a) {
    asm volatile("ldmatrix.sync.aligned.m8n8.x2.shared.b16 {%0,%1}, [%2];"
                 : "=r"(d[0]), "=r"(d[1]) : "r"(a));
}
__device__ __forceinline__ void mma_f16(float* c, const unsigned* a, const unsigned* b) {
    asm volatile(
        "mma.sync.aligned.m16n8k16.row.col.f32.f16.f16.f32 "
        "{%0,%1,%2,%3}, {%4,%5,%6,%7}, {%8,%9}, {%0,%1,%2,%3};"
        : "+f"(c[0]), "+f"(c[1]), "+f"(c[2]), "+f"(c[3])
        : "r"(a[0]), "r"(a[1]), "r"(a[2]), "r"(a[3]), "r"(b[0]), "r"(b[1]));
}

// ----------------------------- prep kernels --------------------------------
__global__ void prep_x(const float* __restrict__ x) {
    __shared__ float sm[32 * 197];
    int cell = blockIdx.x;              // (b'*6 + s')*6 + t'
    int ci0 = blockIdx.y * 32;
    int bp = cell / 36;
    int sp = (cell / 6) % 6;
    int tp = cell % 6;
    int rbase = cell * 196;
    int tid = threadIdx.x;
    bool pad = (sp == 0) | (sp == 5) | (tp == 0) | (tp == 5);
    if (!pad) {
        int b = bp * 4 + (sp - 1);
        int t = tp - 1;
        long xbase = (long)(b * CIN + ci0) * 784 + t * 196;
        for (int l = tid; l < 32 * 196; l += 256) {
            int i = l / 196, p = l - i * 196;
            sm[i * 197 + p] = x[xbase + (long)i * 784 + p];
        }
        __syncthreads();
        for (int l = tid; l < 196 * 16; l += 256) {
            int p = l >> 4, j = l & 15;
            __half2 v = __floats2half2_rn(sm[(2 * j) * 197 + p], sm[(2 * j + 1) * 197 + p]);
            ((__half2*)&g_Xt[(long)(rbase + p) * CIN + ci0])[j] = v;
        }
    } else {
        __half2 z = __floats2half2_rn(0.0f, 0.0f);
        for (int l = tid; l < 196 * 16; l += 256) {
            int p = l >> 4, j = l & 15;
            ((__half2*)&g_Xt[(long)(rbase + p) * CIN + ci0])[j] = z;
        }
    }
}

__global__ void prep_w(const float* __restrict__ W) {
    long t = (long)blockIdx.x * 256 + threadIdx.x;   // co*1024 + ci
    const float* p = W + t * 9;
    float v[9];
#pragma unroll
    for (int k = 0; k < 9; k++) v[k] = p[k];
#pragma unroll
    for (int k = 0; k < 9; k++) g_Wt[(long)k * (COUT * CIN) + t] = __float2half_rn(v[k]);
}

// ----------------------------- main GEMM -----------------------------------
__global__ void __launch_bounds__(128, 2) conv_main(const float* __restrict__ x,
                                                    float* __restrict__ out) {
    extern __shared__ __align__(16) char smem[];
    const int tid = threadIdx.x, wid = tid >> 5, lid = tid & 31;
    const int gid = lid >> 2, tig = lid & 3;
    const int mtile = blockIdx.x, ntile = blockIdx.y;
    const int wm = (wid >> 1) * 64;     // warp m offset {0,64}
    const int wn = (wid & 1) * 56;      // warp n offset {0,56}

    __shared__ int rbase_s[NT];
    if (tid < NT) {
        int q = ntile * NT + tid;
        int b = q / 784;
        int rem = q - b * 784;
        int t = rem / 196;
        int p = rem - t * 196;
        rbase_s[tid] = (b >> 2) * 7056 + (b & 3) * 1176 + t * 196 + p;
    }
    __syncthreads();

    // producer cp.async addresses: A 1024 chunks (8/thr), B 896 chunks (7/thr)
    unsigned gA[8], sA[8], gB[7], sB[7];
#pragma unroll
    for (int k = 0; k < 8; k++) {
        int c = tid + 128 * k;
        int row = c >> 3, j = c & 7;             // 8 x 16B = 128B (64 halves)
        gA[k] = (unsigned)((mtile * MT + row) * 2048 + j * 16);
        sA[k] = (unsigned)(OFF_STAGE + row * ROWB + j * 16);
    }
#pragma unroll
    for (int k = 0; k < 7; k++) {
        int c = tid + 128 * k;
        int n = c >> 3, j = c & 7;
        gB[k] = (unsigned)(rbase_s[n] * 2048 + j * 16);
        sB[k] = (unsigned)(OFF_STAGE + A_BYTES + n * ROWB + j * 16);
    }
    const unsigned sb = s2u(smem);
    const char* WtB = (const char*)g_Wt;
    const char* XtB = (const char*)g_Xt;

    // ldmatrix per-lane base addresses
    const int lm = lid >> 3, lr = lid & 7;
    const unsigned aBase = sb + OFF_STAGE +
        (unsigned)((wm + (lm & 1) * 8 + lr) * ROWB + (lm >> 1) * 16);
    const unsigned bBase = sb + OFF_STAGE + A_BYTES +
        (unsigned)((wn + (lm >> 1) * 8 + lr) * ROWB + (lm & 1) * 16);
    const unsigned b6Base = sb + OFF_STAGE + A_BYTES +
        (unsigned)((wn + 48 + lr) * ROWB + (lm & 1) * 16);

    float acc[4][7][4];
#pragma unroll
    for (int i = 0; i < 4; i++)
#pragma unroll
        for (int j = 0; j < 7; j++)
#pragma unroll
            for (int k = 0; k < 4; k++) acc[i][j][k] = 0.0f;

    auto issue = [&](int it, int slot) {
        if (it < ITERS) {
            int tap = it >> 4, kc = it & 15;
            int ks = tap / 3, kt = tap - ks * 3;
            unsigned soA = (unsigned)tap * 2097152u + (unsigned)kc * 128u;
            unsigned soB = (unsigned)(ks * 1176 + kt * 196) * 2048u + (unsigned)kc * 128u;
            unsigned st = (unsigned)slot * STAGE_BYTES;
#pragma unroll
            for (int k = 0; k < 8; k++) cp16(sb + sA[k] + st, WtB + gA[k] + soA);
#pragma unroll
            for (int k = 0; k < 7; k++) cp16(sb + sB[k] + st, XtB + gB[k] + soB);
        }
        cp_commit();
    };

    issue(0, 0);
    issue(1, 1);

    int cs = 0, ps = 2;
#pragma unroll 1
    for (int it = 0; it < ITERS; ++it) {
        cp_wait1();
        __syncthreads();
        issue(it + 2, ps);
        ps = (ps == STAGES - 1) ? 0 : ps + 1;
        const unsigned stg = (unsigned)cs * STAGE_BYTES;
        cs = (cs == STAGES - 1) ? 0 : cs + 1;
#pragma unroll
        for (int kk = 0; kk < 4; kk++) {       // 4 x K16 = 64 halves
            unsigned a[4][4], b[7][2];
#pragma unroll
            for (int im = 0; im < 4; im++)
                ldsm4(a[im], aBase + stg + (unsigned)(im * (16 * ROWB) + kk * 32));
#pragma unroll
            for (int p = 0; p < 3; p++) {
                unsigned d[4];
                ldsm4(d, bBase + stg + (unsigned)(p * (16 * ROWB) + kk * 32));
                b[2 * p][0] = d[0]; b[2 * p][1] = d[1];       // n-tile p*2
                b[2 * p + 1][0] = d[2]; b[2 * p + 1][1] = d[3]; // n-tile p*2+1
            }
            ldsm2(b[6], b6Base + stg + (unsigned)(kk * 32));
#pragma unroll
            for (int im = 0; im < 4; im++)
#pragma unroll
                for (int in = 0; in < 7; in++) mma_f16(acc[im][in], a[im], b[in]);
        }
    }

    // ------------------------- epilogue: residual add -----------------------
#pragma unroll
    for (int im = 0; im < 4; im++) {
        int m0 = mtile * MT + wm + im * 16 + gid;       // co row (and +8)
#pragma unroll
        for (int in = 0; in < 7; in++) {
            int q = ntile * NT + wn + in * 8 + 2 * tig; // even start => pair in-bounds
            int b = q / 784;
            int rem = q - b * 784;
            int off0 = b * 802816 + m0 * 784 + rem;
            int off1 = off0 + 8 * 784;
            float2 x0 = *(const float2*)(x + off0);
            float2 x1 = *(const float2*)(x + off1);
            float2 o0 = make_float2(acc[im][in][0] + x0.x, acc[im][in][1] + x0.y);
            float2 o1 = make_float2(acc[im][in][2] + x1.x, acc[im][in][3] + x1.y);
            *(float2*)(out + off0) = o0;
            *(float2*)(out + off1) = o1;
        }
    }
}

// ----------------------------- launch --------------------------------------
extern "C" void kernel_launch(void* const* d_in, const int* in_sizes, int n_in,
                              void* d_out, int out_size) {
    const float* x = (const float*)d_in[0];
    const float* W = (const float*)d_in[1];
    if (n_in >= 2 && in_sizes[0] != 8 * 1024 * 4 * 14 * 14) {  // robustness
        x = (const float*)d_in[1];
        W = (const float*)d_in[0];
    }
    float* out = (float*)d_out;

    prep_w<<<4096, 256>>>(W);
    dim3 gx(72, 32);
    prep_x<<<gx, 256>>>(x);

    cudaFuncSetAttribute(conv_main, cudaFuncAttributeMaxDynamicSharedMemorySize, SMEM_MAIN);
    dim3 grid(MTILES, NTILES);
    conv_main<<<grid, 128, SMEM_MAIN>>>(x, out);
}